// round 3
// baseline (speedup 1.0000x reference)
#include <cuda_runtime.h>
#include <cuda_bf16.h>

// Transposed soft-perm matrices: g_Pt[w][j][i] = P_w[i][j], row stride 12 floats
// (48B, 16B-aligned) so pairs (i,i+1) are adjacent for f32x2 FMA.
__device__ float g_Pt[2][10][12];
__device__ unsigned int g_tile_counter;

__global__ void prep_softperm_kernel(const float* __restrict__ W1,
                                     const float* __restrict__ W2,
                                     unsigned int counter_init) {
    int t = threadIdx.x;
    if (t == 31) g_tile_counter = counter_init;  // reset every replay (determinism)
    if (t < 20) {
        const float* W = (t < 10) ? W1 : W2;
        int r = t % 10;
        int w = t / 10;
        float row[10];
        float lo = 1e30f, hi = -1e30f;
#pragma unroll
        for (int j = 0; j < 10; ++j) {
            row[j] = W[r * 10 + j];
            lo = fminf(lo, row[j]);
            hi = fmaxf(hi, row[j]);
        }
        float invr = 1.0f / (hi - lo + 1e-8f);
        float s = 0.0f;
#pragma unroll
        for (int j = 0; j < 10; ++j) {
            row[j] = (row[j] - lo) * invr;
            s += row[j];
        }
        float invs = 1.0f / (s + 1e-8f);
#pragma unroll
        for (int j = 0; j < 10; ++j)
            g_Pt[w][j][r] = row[j] * invs;   // transposed store
    }
}

using u64 = unsigned long long;

__device__ __forceinline__ void fma2(u64& d, u64 a, u64 b) {
    asm("fma.rn.f32x2 %0, %1, %2, %0;" : "+l"(d) : "l"(a), "l"(b));
}
__device__ __forceinline__ u64 fma2n(u64 a, u64 b, u64 c) {
    u64 d;
    asm("fma.rn.f32x2 %0, %1, %2, %3;" : "=l"(d) : "l"(a), "l"(b), "l"(c));
    return d;
}
__device__ __forceinline__ u64 pack2(float x, float y) {
    u64 d;
    asm("mov.b64 %0, {%1, %2};" : "=l"(d) : "f"(x), "f"(y));
    return d;
}
__device__ __forceinline__ void unpack2(u64 v, float& x, float& y) {
    asm("mov.b64 {%0, %1}, %2;" : "=f"(x), "=f"(y) : "l"(v));
}
__device__ __forceinline__ void cp_async16(void* smem, const void* gmem) {
    unsigned s = (unsigned)__cvta_generic_to_shared(smem);
    asm volatile("cp.async.cg.shared.global [%0], [%1], 16;" :: "r"(s), "l"(gmem));
}
__device__ __forceinline__ void cp_commit() {
    asm volatile("cp.async.commit_group;");
}
template <int N>
__device__ __forceinline__ void cp_wait() {
    asm volatile("cp.async.wait_group %0;" :: "n"(N));
}

constexpr int TILE = 256;   // rows per tile (== blockDim.x)

__global__ __launch_bounds__(TILE, 4)
void bacon_fused_kernel(const float* __restrict__ p1,
                        const float* __restrict__ p2,
                        float* __restrict__ out,
                        int B, int ntiles) {
    // double-buffered input staging; each buffer also reused for output staging
    __shared__ __align__(16) float sb[2][5120];
    __shared__ __align__(16) float sPt[2][10][12];
    __shared__ int s_next;

    const int tid = threadIdx.x;

    // load transposed P into shared (240 floats)
    if (tid < 240) ((float*)sPt)[tid] = ((const float*)g_Pt)[tid];

    auto load_tile = [&](int buf, int t) {
        size_t base = (size_t)t * TILE * 10;
        int rows = min(TILE, B - t * TILE);
        float* s = sb[buf];
        if (rows == TILE) {
            const float4* g1 = (const float4*)(p1 + base);
            const float4* g2 = (const float4*)(p2 + base);
#pragma unroll
            for (int i = tid; i < 640; i += TILE) {
                cp_async16(&s[i * 4], &g1[i]);
                cp_async16(&s[2560 + i * 4], &g2[i]);
            }
        } else {
            int n = rows * 10;
            for (int i = tid; i < n; i += TILE) {
                s[i] = p1[base + i];
                s[2560 + i] = p2[base + i];
            }
        }
    };

    int cur = blockIdx.x;            // static first tile (grid <= ntiles)
    load_tile(0, cur);
    cp_commit();

    // grab-ahead: fetch next tile id + start its load immediately
    if (tid == 0) s_next = (int)atomicAdd(&g_tile_counter, 1u);
    __syncthreads();
    int nxt = s_next;
    if (nxt < ntiles) { load_tile(1, nxt); cp_commit(); }

    int p = 0;
    while (true) {
        if (nxt < ntiles) cp_wait<1>(); else cp_wait<0>();
        __syncthreads();

        const int t = cur;
        const int nrows = min(TILE, B - t * TILE);
        const bool active = (tid < nrows);
        const float* s = sb[p];

        float u[10], v[10];
        float prod[19];

        if (active) {
            // matmul: l1 = a . P1^T, l2 = b . P2^T, using packed f32x2 FMA.
            u64 acc1[5], acc2[5];
#pragma unroll
            for (int q = 0; q < 5; ++q) { acc1[q] = 0ULL; acc2[q] = 0ULL; }

#pragma unroll
            for (int jj = 0; jj < 5; ++jj) {
                float2 av = *(const float2*)&s[tid * 10 + jj * 2];
                float2 bv = *(const float2*)&s[2560 + tid * 10 + jj * 2];
#pragma unroll
                for (int h = 0; h < 2; ++h) {
                    int j = jj * 2 + h;
                    float aj = h ? av.y : av.x;
                    float bj = h ? bv.y : bv.x;
                    u64 a2 = pack2(aj, aj);
                    u64 b2 = pack2(bj, bj);
                    const ulonglong2* r1 = (const ulonglong2*)&sPt[0][j][0];
                    const ulonglong2* r2 = (const ulonglong2*)&sPt[1][j][0];
                    ulonglong2 p01 = r1[0], p23 = r1[1];
                    u64 p4 = ((const u64*)&sPt[0][j][0])[4];
                    ulonglong2 q01 = r2[0], q23 = r2[1];
                    u64 q4 = ((const u64*)&sPt[1][j][0])[4];
                    fma2(acc1[0], a2, p01.x);
                    fma2(acc1[1], a2, p01.y);
                    fma2(acc1[2], a2, p23.x);
                    fma2(acc1[3], a2, p23.y);
                    fma2(acc1[4], a2, p4);
                    fma2(acc2[0], b2, q01.x);
                    fma2(acc2[1], b2, q01.y);
                    fma2(acc2[2], b2, q23.x);
                    fma2(acc2[3], b2, q23.y);
                    fma2(acc2[4], b2, q4);
                }
            }

            // u_i = clip(1 - l1_i), v_i = clip(1 - l2_i)
            const u64 NEG1 = pack2(-1.0f, -1.0f);
            const u64 ONE1 = pack2(1.0f, 1.0f);
#pragma unroll
            for (int q = 0; q < 5; ++q) {
                float x, y;
                unpack2(fma2n(acc1[q], NEG1, ONE1), x, y);
                u[2 * q]     = fminf(fmaxf(x, 1e-6f), 1.0f - 1e-6f);
                u[2 * q + 1] = fminf(fmaxf(y, 1e-6f), 1.0f - 1e-6f);
                unpack2(fma2n(acc2[q], NEG1, ONE1), x, y);
                v[2 * q]     = fminf(fmaxf(x, 1e-6f), 1.0f - 1e-6f);
                v[2 * q + 1] = fminf(fmaxf(y, 1e-6f), 1.0f - 1e-6f);
            }

            // y_k = 1 - prod_{i+j=k} max(u_i, v_j)
#pragma unroll
            for (int k = 0; k < 19; ++k) prod[k] = 1.0f;
#pragma unroll
            for (int i = 0; i < 10; ++i) {
#pragma unroll
                for (int j = 0; j < 10; ++j)
                    prod[i + j] *= fmaxf(u[i], v[j]);
            }

            float sum = 0.0f;
#pragma unroll
            for (int k = 0; k < 19; ++k) {
                prod[k] = 1.0f - prod[k];
                sum += prod[k];
            }
            float inv = __fdividef(1.0f, sum + 1e-9f);
#pragma unroll
            for (int k = 0; k < 19; ++k) prod[k] *= inv;
        }

        __syncthreads();   // all reads of sb[p] done -> reuse for output staging
        if (active) {
#pragma unroll
            for (int k = 0; k < 19; ++k)
                sb[p][tid * 19 + k] = prod[k];   // stride 19: conflict-free
        }
        __syncthreads();

        float* ob = out + (size_t)t * TILE * 19;
        if (nrows == TILE) {
            float4* ov = (float4*)ob;
            const float4* sv = (const float4*)sb[p];
#pragma unroll
            for (int i = tid; i < 1216; i += TILE) ov[i] = sv[i];
        } else {
            int n = nrows * 19;
            for (int i = tid; i < n; i += TILE) ob[i] = sb[p][i];
        }

        if (nxt >= ntiles) break;
        cur = nxt;
        p ^= 1;

        // grab-ahead the following tile and prefetch it into the buffer whose
        // output copy just completed (barrier below orders the copy's reads).
        if (tid == 0) s_next = (int)atomicAdd(&g_tile_counter, 1u);
        __syncthreads();               // also orders output-copy reads vs prefetch writes
        nxt = s_next;
        if (nxt < ntiles) { load_tile(1 - p, nxt); cp_commit(); }
    }
}

extern "C" void kernel_launch(void* const* d_in, const int* in_sizes, int n_in,
                              void* d_out, int out_size) {
    const float* p1 = (const float*)d_in[0];
    const float* p2 = (const float*)d_in[1];
    const float* W1 = (const float*)d_in[2];
    const float* W2 = (const float*)d_in[3];
    float* out = (float*)d_out;

    int B = in_sizes[0] / 10;
    int ntiles = (B + TILE - 1) / TILE;

    // one full wave at occupancy 4 on 148 SMs
    int G = 592;
    if (G > ntiles) G = ntiles;
    if (G < 1) G = 1;

    prep_softperm_kernel<<<1, 32>>>(W1, W2, (unsigned int)G);
    bacon_fused_kernel<<<G, TILE>>>(p1, p2, out, B, ntiles);
}

// round 4
// speedup vs baseline: 1.1555x; 1.1555x over previous
#include <cuda_runtime.h>
#include <cuda_bf16.h>

using u64 = unsigned long long;

__device__ __forceinline__ void fma2(u64& d, u64 a, u64 b) {
    asm("fma.rn.f32x2 %0, %1, %2, %0;" : "+l"(d) : "l"(a), "l"(b));
}
__device__ __forceinline__ u64 fma2n(u64 a, u64 b, u64 c) {
    u64 d;
    asm("fma.rn.f32x2 %0, %1, %2, %3;" : "=l"(d) : "l"(a), "l"(b), "l"(c));
    return d;
}
__device__ __forceinline__ u64 pack2(float x, float y) {
    u64 d;
    asm("mov.b64 %0, {%1, %2};" : "=l"(d) : "f"(x), "f"(y));
    return d;
}
__device__ __forceinline__ void unpack2(u64 v, float& x, float& y) {
    asm("mov.b64 {%0, %1}, %2;" : "=f"(x), "=f"(y) : "l"(v));
}

constexpr int TILE = 256;   // rows per tile (== blockDim.x)
constexpr int WARPS = 8;

// Core per-row computation. a,b = the 10 input probs for this row.
// sPt = transposed soft-perm matrices (stride-12 rows).
__device__ __forceinline__ void compute_row(const float2 av[5], const float2 bv[5],
                                            const float (*sPt)[10][12],
                                            float res[19]) {
    u64 acc1[5], acc2[5];
#pragma unroll
    for (int q = 0; q < 5; ++q) { acc1[q] = 0ULL; acc2[q] = 0ULL; }

#pragma unroll
    for (int jj = 0; jj < 5; ++jj) {
#pragma unroll
        for (int h = 0; h < 2; ++h) {
            int j = jj * 2 + h;
            float aj = h ? av[jj].y : av[jj].x;
            float bj = h ? bv[jj].y : bv[jj].x;
            u64 a2 = pack2(aj, aj);
            u64 b2 = pack2(bj, bj);
            const ulonglong2* r1 = (const ulonglong2*)&sPt[0][j][0];
            const ulonglong2* r2 = (const ulonglong2*)&sPt[1][j][0];
            ulonglong2 p01 = r1[0], p23 = r1[1];
            u64 p4 = ((const u64*)&sPt[0][j][0])[4];
            ulonglong2 q01 = r2[0], q23 = r2[1];
            u64 q4 = ((const u64*)&sPt[1][j][0])[4];
            fma2(acc1[0], a2, p01.x);
            fma2(acc1[1], a2, p01.y);
            fma2(acc1[2], a2, p23.x);
            fma2(acc1[3], a2, p23.y);
            fma2(acc1[4], a2, p4);
            fma2(acc2[0], b2, q01.x);
            fma2(acc2[1], b2, q01.y);
            fma2(acc2[2], b2, q23.x);
            fma2(acc2[3], b2, q23.y);
            fma2(acc2[4], b2, q4);
        }
    }

    float u[10], v[10];
    const u64 NEG1 = pack2(-1.0f, -1.0f);
    const u64 ONE1 = pack2(1.0f, 1.0f);
#pragma unroll
    for (int q = 0; q < 5; ++q) {
        float x, y;
        unpack2(fma2n(acc1[q], NEG1, ONE1), x, y);
        u[2 * q]     = fminf(fmaxf(x, 1e-6f), 1.0f - 1e-6f);
        u[2 * q + 1] = fminf(fmaxf(y, 1e-6f), 1.0f - 1e-6f);
        unpack2(fma2n(acc2[q], NEG1, ONE1), x, y);
        v[2 * q]     = fminf(fmaxf(x, 1e-6f), 1.0f - 1e-6f);
        v[2 * q + 1] = fminf(fmaxf(y, 1e-6f), 1.0f - 1e-6f);
    }

    // y_k = 1 - prod_{i+j=k} max(u_i, v_j)
    float prod[19];
#pragma unroll
    for (int j = 0; j < 10; ++j) prod[j] = fmaxf(u[0], v[j]);     // i = 0 row
#pragma unroll
    for (int i = 1; i < 10; ++i) prod[9 + i] = fmaxf(u[i], v[9]); // j = 9 col
#pragma unroll
    for (int i = 1; i < 10; ++i) {
#pragma unroll
        for (int j = 0; j < 9; ++j)
            prod[i + j] *= fmaxf(u[i], v[j]);
    }

    float sum = 0.0f;
#pragma unroll
    for (int k = 0; k < 19; ++k) {
        res[k] = 1.0f - prod[k];
        sum += res[k];
    }
    float inv = __fdividef(1.0f, sum + 1e-9f);
#pragma unroll
    for (int k = 0; k < 19; ++k) res[k] *= inv;
}

__global__ __launch_bounds__(TILE, 4)
void bacon_kernel(const float* __restrict__ p1,
                  const float* __restrict__ p2,
                  const float* __restrict__ W1,
                  const float* __restrict__ W2,
                  float* __restrict__ out,
                  int B, int ntiles, int tpc) {
    // per-warp private staging slices (640 floats): input p1[0,320)+p2[320,640),
    // reused for output staging (608 floats). No block barriers in main loop.
    __shared__ __align__(16) float ws[WARPS][640];
    __shared__ __align__(16) float sPt[2][10][12];   // transposed: sPt[w][j][i]

    const int tid  = threadIdx.x;
    const int lane = tid & 31;
    const int w    = tid >> 5;

    // Inline soft-perm prep (replaces separate launch): threads 0..19.
    if (tid < 20) {
        const float* W = (tid < 10) ? W1 : W2;
        int r = tid % 10, m = tid / 10;
        float row[10];
        float lo = 1e30f, hi = -1e30f;
#pragma unroll
        for (int j = 0; j < 10; ++j) {
            row[j] = W[r * 10 + j];
            lo = fminf(lo, row[j]);
            hi = fmaxf(hi, row[j]);
        }
        float invr = 1.0f / (hi - lo + 1e-8f);
        float s = 0.0f;
#pragma unroll
        for (int j = 0; j < 10; ++j) {
            row[j] = (row[j] - lo) * invr;
            s += row[j];
        }
        float invs = 1.0f / (s + 1e-8f);
#pragma unroll
        for (int j = 0; j < 10; ++j)
            sPt[m][j][r] = row[j] * invs;
    }
    __syncthreads();   // the only block barrier

    const int t_end = min((blockIdx.x + 1) * tpc, ntiles);

    for (int t = blockIdx.x * tpc; t < t_end; ++t) {
        const int rowbase = t * TILE + w * 32;   // this warp's 32 rows
        float* slice = ws[w];

        if (rowbase + 32 <= B) {
            // ---- fast path: full warp of rows, fully coalesced ----
            // stage inputs: 80 float4 per array per warp
            const float4* g1 = (const float4*)p1 + (size_t)t * 640 + w * 80;
            const float4* g2 = (const float4*)p2 + (size_t)t * 640 + w * 80;
            float4* s1 = (float4*)slice;
            float4* s2 = (float4*)(slice + 320);
#pragma unroll
            for (int i = 0; i < 3; ++i) {
                int idx = lane + i * 32;
                if (idx < 80) {
                    s1[idx] = g1[idx];
                    s2[idx] = g2[idx];
                }
            }
            __syncwarp();

            float2 av[5], bv[5];
#pragma unroll
            for (int jj = 0; jj < 5; ++jj) {
                av[jj] = *(const float2*)&slice[lane * 10 + jj * 2];
                bv[jj] = *(const float2*)&slice[320 + lane * 10 + jj * 2];
            }
            __syncwarp();   // all lanes' input reads done before output overwrites

            float res[19];
            compute_row(av, bv, sPt, res);

            // stage output (stride 19: conflict-free), then coalesced float4 store
#pragma unroll
            for (int k = 0; k < 19; ++k) slice[lane * 19 + k] = res[k];
            __syncwarp();

            float4* og = (float4*)out + (size_t)t * 1216 + w * 152;
            const float4* sv = (const float4*)slice;
#pragma unroll
            for (int i = 0; i < 5; ++i) {
                int idx = lane + i * 32;
                if (idx < 152) og[idx] = sv[idx];
            }
            __syncwarp();   // copy reads done before next tile's staging
        } else if (rowbase < B) {
            // ---- tail path: scalar, no smem ----
            int row = rowbase + lane;
            if (row < B) {
                float2 av[5], bv[5];
#pragma unroll
                for (int jj = 0; jj < 5; ++jj) {
                    av[jj] = *(const float2*)&p1[(size_t)row * 10 + jj * 2];
                    bv[jj] = *(const float2*)&p2[(size_t)row * 10 + jj * 2];
                }
                float res[19];
                compute_row(av, bv, sPt, res);
#pragma unroll
                for (int k = 0; k < 19; ++k)
                    out[(size_t)row * 19 + k] = res[k];
            }
            __syncwarp();
        }
    }
}

extern "C" void kernel_launch(void* const* d_in, const int* in_sizes, int n_in,
                              void* d_out, int out_size) {
    const float* p1 = (const float*)d_in[0];
    const float* p2 = (const float*)d_in[1];
    const float* W1 = (const float*)d_in[2];
    const float* W2 = (const float*)d_in[3];
    float* out = (float*)d_out;

    int B = in_sizes[0] / 10;
    int ntiles = (B + TILE - 1) / TILE;

    // tiles per CTA chosen so the grid is one balanced wave at occupancy 4
    int tpc = (ntiles + 592 - 1) / 592;
    if (tpc < 1) tpc = 1;
    int G = (ntiles + tpc - 1) / tpc;

    bacon_kernel<<<G, TILE>>>(p1, p2, W1, W2, out, B, ntiles, tpc);
}

// round 5
// speedup vs baseline: 1.3113x; 1.1348x over previous
#include <cuda_runtime.h>
#include <cuda_bf16.h>

using u64 = unsigned long long;

__device__ __forceinline__ void fma2(u64& d, u64 a, u64 b) {
    asm("fma.rn.f32x2 %0, %1, %2, %0;" : "+l"(d) : "l"(a), "l"(b));
}
__device__ __forceinline__ u64 fma2n(u64 a, u64 b, u64 c) {
    u64 d;
    asm("fma.rn.f32x2 %0, %1, %2, %3;" : "=l"(d) : "l"(a), "l"(b), "l"(c));
    return d;
}
__device__ __forceinline__ u64 pack2(float x, float y) {
    u64 d;
    asm("mov.b64 %0, {%1, %2};" : "=l"(d) : "f"(x), "f"(y));
    return d;
}
__device__ __forceinline__ void unpack2(u64 v, float& x, float& y) {
    asm("mov.b64 {%0, %1}, %2;" : "=f"(x), "=f"(y) : "l"(v));
}
__device__ __forceinline__ void cp_async16(void* smem, const void* gmem) {
    unsigned s = (unsigned)__cvta_generic_to_shared(smem);
    asm volatile("cp.async.cg.shared.global [%0], [%1], 16;" :: "r"(s), "l"(gmem));
}
__device__ __forceinline__ void cp_commit() {
    asm volatile("cp.async.commit_group;");
}
template <int N>
__device__ __forceinline__ void cp_wait() {
    asm volatile("cp.async.wait_group %0;" :: "n"(N));
}

constexpr int TILE = 256;   // rows per tile (== blockDim.x)
constexpr int WARPS = 8;

// Core per-row computation. av/bv = the 10 input probs (packed pairs).
// sPt = transposed soft-perm matrices (stride-12 rows).
__device__ __forceinline__ void compute_row(const float2 av[5], const float2 bv[5],
                                            const float (*sPt)[10][12],
                                            float res[19]) {
    u64 acc1[5], acc2[5];
#pragma unroll
    for (int q = 0; q < 5; ++q) { acc1[q] = 0ULL; acc2[q] = 0ULL; }

#pragma unroll
    for (int jj = 0; jj < 5; ++jj) {
#pragma unroll
        for (int h = 0; h < 2; ++h) {
            int j = jj * 2 + h;
            float aj = h ? av[jj].y : av[jj].x;
            float bj = h ? bv[jj].y : bv[jj].x;
            u64 a2 = pack2(aj, aj);
            u64 b2 = pack2(bj, bj);
            const ulonglong2* r1 = (const ulonglong2*)&sPt[0][j][0];
            const ulonglong2* r2 = (const ulonglong2*)&sPt[1][j][0];
            ulonglong2 p01 = r1[0], p23 = r1[1];
            u64 p4 = ((const u64*)&sPt[0][j][0])[4];
            ulonglong2 q01 = r2[0], q23 = r2[1];
            u64 q4 = ((const u64*)&sPt[1][j][0])[4];
            fma2(acc1[0], a2, p01.x);
            fma2(acc1[1], a2, p01.y);
            fma2(acc1[2], a2, p23.x);
            fma2(acc1[3], a2, p23.y);
            fma2(acc1[4], a2, p4);
            fma2(acc2[0], b2, q01.x);
            fma2(acc2[1], b2, q01.y);
            fma2(acc2[2], b2, q23.x);
            fma2(acc2[3], b2, q23.y);
            fma2(acc2[4], b2, q4);
        }
    }

    float u[10], v[10];
    const u64 NEG1 = pack2(-1.0f, -1.0f);
    const u64 ONE1 = pack2(1.0f, 1.0f);
#pragma unroll
    for (int q = 0; q < 5; ++q) {
        float x, y;
        unpack2(fma2n(acc1[q], NEG1, ONE1), x, y);
        u[2 * q]     = fminf(fmaxf(x, 1e-6f), 1.0f - 1e-6f);
        u[2 * q + 1] = fminf(fmaxf(y, 1e-6f), 1.0f - 1e-6f);
        unpack2(fma2n(acc2[q], NEG1, ONE1), x, y);
        v[2 * q]     = fminf(fmaxf(x, 1e-6f), 1.0f - 1e-6f);
        v[2 * q + 1] = fminf(fmaxf(y, 1e-6f), 1.0f - 1e-6f);
    }

    // y_k = 1 - prod_{i+j=k} max(u_i, v_j)
    float prod[19];
#pragma unroll
    for (int j = 0; j < 10; ++j) prod[j] = fmaxf(u[0], v[j]);     // i = 0 row
#pragma unroll
    for (int i = 1; i < 10; ++i) prod[9 + i] = fmaxf(u[i], v[9]); // j = 9 col
#pragma unroll
    for (int i = 1; i < 10; ++i) {
#pragma unroll
        for (int j = 0; j < 9; ++j)
            prod[i + j] *= fmaxf(u[i], v[j]);
    }

    float sum = 0.0f;
#pragma unroll
    for (int k = 0; k < 19; ++k) {
        res[k] = 1.0f - prod[k];
        sum += res[k];
    }
    float inv = __fdividef(1.0f, sum + 1e-9f);
#pragma unroll
    for (int k = 0; k < 19; ++k) res[k] *= inv;
}

__global__ __launch_bounds__(TILE, 4)
void bacon_kernel(const float* __restrict__ p1,
                  const float* __restrict__ p2,
                  const float* __restrict__ W1,
                  const float* __restrict__ W2,
                  float* __restrict__ out,
                  int B, int ntiles) {
    // per-warp private double-buffered staging slices (2 x 640 floats):
    // buffer = p1 rows [0,320) + p2 rows [320,640); reused for output staging.
    // No block barriers after init; cp.async is per-thread, sync via __syncwarp.
    __shared__ __align__(16) float ws[WARPS][2][640];
    __shared__ __align__(16) float sPt[2][10][12];   // transposed: sPt[m][j][i]

    const int tid  = threadIdx.x;
    const int lane = tid & 31;
    const int w    = tid >> 5;
    const int G    = gridDim.x;

    // Inline soft-perm prep: threads 0..19.
    if (tid < 20) {
        const float* W = (tid < 10) ? W1 : W2;
        int r = tid % 10, m = tid / 10;
        float row[10];
        float lo = 1e30f, hi = -1e30f;
#pragma unroll
        for (int j = 0; j < 10; ++j) {
            row[j] = W[r * 10 + j];
            lo = fminf(lo, row[j]);
            hi = fmaxf(hi, row[j]);
        }
        float invr = 1.0f / (hi - lo + 1e-8f);
        float s = 0.0f;
#pragma unroll
        for (int j = 0; j < 10; ++j) {
            row[j] = (row[j] - lo) * invr;
            s += row[j];
        }
        float invs = 1.0f / (s + 1e-8f);
#pragma unroll
        for (int j = 0; j < 10; ++j)
            sPt[m][j][r] = row[j] * invs;
    }
    __syncthreads();   // the only block barrier

    // stage this warp's 32-row slab of tile t into buffer buf (fast path only)
    auto stage = [&](int buf, int t) {
        // exactly 5 x 16B cp.async per lane (160 float4 total per warp slice)
        const float4* g1 = (const float4*)p1 + (size_t)t * 640 + w * 80;
        const float4* g2 = (const float4*)p2 + (size_t)t * 640 + w * 80;
        float4* s = (float4*)ws[w][buf];
#pragma unroll
        for (int i = 0; i < 5; ++i) {
            int idx = lane + i * 32;
            const float4* src = (idx < 80) ? (g1 + idx) : (g2 + (idx - 80));
            cp_async16(&s[idx], src);
        }
    };

    int cur = blockIdx.x;
    if (cur >= ntiles) return;
    const bool cur_full0 = (cur * TILE + (w + 1) * 32 <= B);
    if (cur_full0) { stage(0, cur); cp_commit(); }

    int p = 0;
    for (; cur < ntiles; cur += G) {
        const int nxt = cur + G;
        const bool cur_full = (cur * TILE + (w + 1) * 32 <= B);
        const bool nxt_full = (nxt < ntiles) && (nxt * TILE + (w + 1) * 32 <= B);

        if (nxt_full) { stage(1 - p, nxt); cp_commit(); }

        if (cur_full) {
            if (nxt_full) cp_wait<1>(); else cp_wait<0>();
            __syncwarp();

            float* slice = ws[w][p];
            float2 av[5], bv[5];
#pragma unroll
            for (int jj = 0; jj < 5; ++jj) {
                av[jj] = *(const float2*)&slice[lane * 10 + jj * 2];
                bv[jj] = *(const float2*)&slice[320 + lane * 10 + jj * 2];
            }
            __syncwarp();   // input reads done before output staging overwrites

            float res[19];
            compute_row(av, bv, sPt, res);

#pragma unroll
            for (int k = 0; k < 19; ++k) slice[lane * 19 + k] = res[k];  // stride 19: conflict-free
            __syncwarp();

            float4* og = (float4*)out + (size_t)cur * 1216 + w * 152;
            const float4* sv = (const float4*)slice;
#pragma unroll
            for (int i = 0; i < 5; ++i) {
                int idx = lane + i * 32;
                if (idx < 152) og[idx] = sv[idx];
            }
            __syncwarp();   // copy reads done before this buffer's next prefetch
        } else {
            // tail slab: scalar, no smem
            cp_wait<0>();
            int row = cur * TILE + w * 32 + lane;
            if (row < B) {
                float2 av[5], bv[5];
#pragma unroll
                for (int jj = 0; jj < 5; ++jj) {
                    av[jj] = *(const float2*)&p1[(size_t)row * 10 + jj * 2];
                    bv[jj] = *(const float2*)&p2[(size_t)row * 10 + jj * 2];
                }
                float res[19];
                compute_row(av, bv, sPt, res);
#pragma unroll
                for (int k = 0; k < 19; ++k)
                    out[(size_t)row * 19 + k] = res[k];
            }
            __syncwarp();
        }
        p ^= 1;
    }
}

extern "C" void kernel_launch(void* const* d_in, const int* in_sizes, int n_in,
                              void* d_out, int out_size) {
    const float* p1 = (const float*)d_in[0];
    const float* p2 = (const float*)d_in[1];
    const float* W1 = (const float*)d_in[2];
    const float* W2 = (const float*)d_in[3];
    float* out = (float*)d_out;

    int B = in_sizes[0] / 10;
    int ntiles = (B + TILE - 1) / TILE;

    // one balanced wave at occupancy 4 on 148 SMs; blocks b < ntiles-G run
    // 2 tiles (b, b+G), the rest run 1 — round-robin spreads the heavy blocks.
    int G = 592;
    if (G > ntiles) G = ntiles;
    if (G < 1) G = 1;

    bacon_kernel<<<G, TILE>>>(p1, p2, W1, W2, out, B, ntiles);
}